// round 2
// baseline (speedup 1.0000x reference)
#include <cuda_runtime.h>

// ---------------------------------------------------------------------------
// 4D ConvTranspose, stride 2, K=3^4, B=4, Ci=Co=64, L=12^4 -> O=25^4.
//
// Parity-class decomposition: output position o_i = 2*m_i + p_i. For an odd
// dim (p=1) exactly one kernel tap (k=1) contributes; for an even dim (p=0)
// taps k=0 (input m) and k=2 (input m-1) contribute (boundary-clipped).
// Each of the 16 classes is a dense GEMM:
//    Out[co, sp] = sum_{ci, t} W[kidx(t)][ci][co] * X[b, ci, m(sp)-d(t)]
// M=64 (co), N=spatial points of the class, K = 64 * 2^(#even dims).
// ---------------------------------------------------------------------------

#define XSB 1327104   // x strides (floats)
#define XSC 20736
#define XS1 1728
#define XS2 144
#define XS3 12
#define OSB 25000000  // out strides
#define OSC 390625
#define OS1 15625
#define OS2 625
#define OS3 25

// Transposed weights: [kidx(81)][ci(64)][co(64)], co contiguous.
__device__ __align__(16) float g_wt[81 * 64 * 64];

__global__ void wt_kernel(const float* __restrict__ w) {
    int idx = blockIdx.x * 256 + threadIdx.x;
    if (idx >= 64 * 64 * 81) return;
    int ci   = idx / 5184;
    int r    = idx - ci * 5184;
    int co   = r / 81;
    int kidx = r - co * 81;
    g_wt[(kidx * 64 + ci) * 64 + co] = w[idx];
}

// Packed dual-fp32 FMA (FFMA2): 2 MACs per issue slot.
__device__ __forceinline__ unsigned long long ffma2(
    unsigned long long a, unsigned long long b, unsigned long long c) {
    unsigned long long d;
    asm("fma.rn.f32x2 %0, %1, %2, %3;" : "=l"(d) : "l"(a), "l"(b), "l"(c));
    return d;
}

__global__ __launch_bounds__(256) void ct4d_kernel(
    const float* __restrict__ x, const float* __restrict__ bias,
    float* __restrict__ out)
{
    const int tid  = threadIdx.x;
    const int c    = blockIdx.z;   // parity class 0..15
    const int b    = blockIdx.y;   // batch
    const int tile = blockIdx.x;   // 64-point spatial tile within class

    const int p1 = (c >> 3) & 1, p2 = (c >> 2) & 1, p3 = (c >> 1) & 1, p4 = c & 1;
    const int n1 = 13 - p1, n2 = 13 - p2, n3 = 13 - p3, n4 = 13 - p4;
    const int Ntot = n1 * n2 * n3 * n4;
    if (tile * 64 >= Ntot) return;

    const int lgT = (1 - p1) + (1 - p2) + (1 - p3) + (1 - p4);
    const int T   = 1 << lgT;          // taps per class: 1..16

    __shared__ __align__(16) float2 Ws2[16][64];  // {w,w} pairs, co contiguous
    __shared__ __align__(16) float  Xs[16][64];
    __shared__ int  offs[16 * 64];                // [t][sp] gather offsets, -1 = OOB
    __shared__ int  kof[16];                      // kidx per tap
    __shared__ signed char dds[4][16];            // per-dim input shift per tap

    // --- tap tables (one thread per tap) ---
    if (tid < T) {
        int rem = tid;
        int pp[4] = {p1, p2, p3, p4};
        int d[4], k[4];
        #pragma unroll
        for (int i = 0; i < 4; i++) {
            if (pp[i] == 0) { d[i] = rem & 1; rem >>= 1; k[i] = 2 * d[i]; }
            else            { d[i] = 0;                  k[i] = 1; }
        }
        kof[tid] = k[0] * 27 + k[1] * 9 + k[2] * 3 + k[3];
        dds[0][tid] = (signed char)d[0]; dds[1][tid] = (signed char)d[1];
        dds[2][tid] = (signed char)d[2]; dds[3][tid] = (signed char)d[3];
    }
    __syncthreads();

    // --- gather-offset table: amortize all 4D index math across the K loop ---
    for (int idx = tid; idx < T * 64; idx += 256) {
        int t = idx >> 6, j = idx & 63;
        int g = tile * 64 + j;
        int off = -1;
        if (g < Ntot) {
            int m4 = g % n4; int q = g / n4;
            int m3 = q % n3; q /= n3;
            int m2 = q % n2; int m1 = q / n2;
            int a1 = m1 - dds[0][t], a2 = m2 - dds[1][t];
            int a3 = m3 - dds[2][t], a4 = m4 - dds[3][t];
            if (((unsigned)a1 < 12u) & ((unsigned)a2 < 12u) &
                ((unsigned)a3 < 12u) & ((unsigned)a4 < 12u))
                off = a1 * XS1 + a2 * XS2 + a3 * XS3 + a4;
        }
        offs[idx] = off;
    }
    // (first __syncthreads inside K loop publishes offs before staging)

    const float* xb = x + b * XSB;
    const int tx = tid & 15, ty = tid >> 4;   // tx -> sp group, ty -> co group

    unsigned long long acc[4][2];
    #pragma unroll
    for (int i = 0; i < 4; i++) { acc[i][0] = 0ull; acc[i][1] = 0ull; }

    const int Ktot = 64 << lgT;
    for (int kb = 0; kb < Ktot; kb += 16) {
        __syncthreads();
        // --- stage one BK=16 slab of W and X ---
        {
            const int row = ty, cg = tx;
            int k  = kb + row;
            int ci = k >> lgT;
            int t  = k & (T - 1);
            const float4 wv = *(const float4*)(g_wt + (kof[t] * 64 + ci) * 64 + cg * 4);
            *(float4*)&Ws2[row][cg * 4 + 0] = make_float4(wv.x, wv.x, wv.y, wv.y);
            *(float4*)&Ws2[row][cg * 4 + 2] = make_float4(wv.z, wv.z, wv.w, wv.w);

            const float* xci = xb + ci * XSC;
            const int*   ot  = offs + t * 64 + cg * 4;
            float v0, v1, v2, v3;
            int o0 = ot[0], o1 = ot[1], o2 = ot[2], o3 = ot[3];
            v0 = (o0 >= 0) ? __ldg(xci + o0) : 0.f;
            v1 = (o1 >= 0) ? __ldg(xci + o1) : 0.f;
            v2 = (o2 >= 0) ? __ldg(xci + o2) : 0.f;
            v3 = (o3 >= 0) ? __ldg(xci + o3) : 0.f;
            *(float4*)&Xs[row][cg * 4] = make_float4(v0, v1, v2, v3);
        }
        __syncthreads();

        // --- 64x64 GEMM microkernel, 4co x 4sp per thread, packed f32x2 ---
        #pragma unroll
        for (int kk = 0; kk < 16; kk++) {
            const ulonglong2 xv  = *(const ulonglong2*)&Xs[kk][tx * 4];
            const ulonglong2 w01 = *(const ulonglong2*)&Ws2[kk][ty * 4];
            const ulonglong2 w23 = *(const ulonglong2*)&Ws2[kk][ty * 4 + 2];
            acc[0][0] = ffma2(w01.x, xv.x, acc[0][0]);
            acc[0][1] = ffma2(w01.x, xv.y, acc[0][1]);
            acc[1][0] = ffma2(w01.y, xv.x, acc[1][0]);
            acc[1][1] = ffma2(w01.y, xv.y, acc[1][1]);
            acc[2][0] = ffma2(w23.x, xv.x, acc[2][0]);
            acc[2][1] = ffma2(w23.x, xv.y, acc[2][1]);
            acc[3][0] = ffma2(w23.y, xv.x, acc[3][0]);
            acc[3][1] = ffma2(w23.y, xv.y, acc[3][1]);
        }
    }

    // --- epilogue: unpack, add bias, strided store into the class sub-grid ---
    float bi[4];
    #pragma unroll
    for (int i = 0; i < 4; i++) bi[i] = bias[ty * 4 + i];
    float* ob = out + b * OSB;

    #pragma unroll
    for (int l = 0; l < 4; l++) {
        int j = tx * 4 + l;
        int g = tile * 64 + j;
        if (g >= Ntot) continue;
        int m4 = g % n4; int q = g / n4;
        int m3 = q % n3; q /= n3;
        int m2 = q % n2; int m1 = q / n2;
        int o = (2 * m1 + p1) * OS1 + (2 * m2 + p2) * OS2 +
                (2 * m3 + p3) * OS3 + (2 * m4 + p4);
        #pragma unroll
        for (int i = 0; i < 4; i++) {
            unsigned long long v = acc[i][l >> 1];
            unsigned u = (l & 1) ? (unsigned)(v >> 32) : (unsigned)(v & 0xffffffffu);
            ob[(ty * 4 + i) * OSC + o] = __uint_as_float(u) + bi[i];
        }
    }
}

extern "C" void kernel_launch(void* const* d_in, const int* in_sizes, int n_in,
                              void* d_out, int out_size) {
    const float* x    = (const float*)d_in[0];
    const float* w    = (const float*)d_in[1];
    const float* bias = (const float*)d_in[2];
    float* out = (float*)d_out;

    wt_kernel<<<(64 * 64 * 81 + 255) / 256, 256>>>(w);

    // 447 = ceil(13^4 / 64) tiles covers the largest class; smaller classes
    // early-exit surplus tiles.
    dim3 grid(447, 4, 16);
    ct4d_kernel<<<grid, 256>>>(x, bias, out);
}

// round 4
// speedup vs baseline: 2.5353x; 2.5353x over previous
#include <cuda_runtime.h>
#include <cuda_bf16.h>
#include <cstdint>

// ---------------------------------------------------------------------------
// 4D ConvTranspose stride2 K=3^4 as 16 parity-class GEMMs on the legacy
// tensor-core path (ldmatrix + mma.sync m16n8k16 bf16, fp32 accum).
//   D[sp=128, co=64] += X[sp, k]·W[co, k],  k = (tap t, ci),  K = 64*T
// bf16 hi/lo split (xh*wh + xh*wl + xl*wh) for fp32-grade accuracy.
// NOTE: harness ptxas target is plain sm_103 -> no tcgen05/TMEM available.
// ---------------------------------------------------------------------------

#define XM 20736            // 12^4 input spatial points
#define OSB 25000000LL
#define OSC 390625
#define OS1 15625
#define OS2 625
#define OS3 25

// prepped operands
__device__ __align__(16) __nv_bfloat16 g_wh[81*64*64];   // [kidx][co][ci]
__device__ __align__(16) __nv_bfloat16 g_wl[81*64*64];
__device__ __align__(16) __nv_bfloat16 g_xh[4L*XM*64];   // [b][m_lin][ci]
__device__ __align__(16) __nv_bfloat16 g_xl[4L*XM*64];

// dynamic SMEM layout (1024B-aligned tiles for the XOR swizzle)
#define SM_A    0           // A_hi: 128 rows x 128B
#define SM_AL   16384       // A_lo
#define SM_BH   32768       // B_hi: 64 rows x 128B
#define SM_BL   40960       // B_lo
#define SM_OFFS 49152       // int[16*128]
#define SM_BIAS 57344       // float[64]
#define SM_KOF  57600       // int[16]
#define SM_DD   57664       // char[16][4]
#define SM_TOTAL 57728

#define SWZ(o) ((o) ^ (((o) >> 3) & 0x70))

// ---------------- prep kernels ----------------
__global__ void wt_prep(const float* __restrict__ w) {
    int idx = blockIdx.x * 256 + threadIdx.x;
    if (idx >= 331776) return;                 // 64*64*81
    int ci = idx / 5184;
    int r  = idx - ci * 5184;
    int co = r / 81;
    int k  = r - co * 81;
    float v = w[idx];
    __nv_bfloat16 h = __float2bfloat16(v);
    __nv_bfloat16 l = __float2bfloat16(v - __bfloat162float(h));
    int o = (k * 64 + co) * 64 + ci;
    g_wh[o] = h; g_wl[o] = l;
}

__global__ void xt_prep(const float* __restrict__ x) {
    __shared__ float s[64][33];
    int b = blockIdx.y, m0 = blockIdx.x * 32, tid = threadIdx.x;
    for (int i = tid; i < 2048; i += 256) {
        int ci = i >> 5, mm = i & 31;
        s[ci][mm] = x[((size_t)(b * 64 + ci)) * XM + m0 + mm];
    }
    __syncthreads();
    int m = tid >> 3, q = tid & 7;
    union { __nv_bfloat16 a[8]; uint4 v; } hv, lv;
    #pragma unroll
    for (int j = 0; j < 8; j++) {
        float v = s[q * 8 + j][m];
        hv.a[j] = __float2bfloat16(v);
        lv.a[j] = __float2bfloat16(v - __bfloat162float(hv.a[j]));
    }
    size_t o = ((size_t)b * XM + m0 + m) * 64 + q * 8;
    *(uint4*)(g_xh + o) = hv.v;
    *(uint4*)(g_xl + o) = lv.v;
}

// ---------------- ptx helpers ----------------
__device__ __forceinline__ uint32_t smem_u32(const void* p) {
    uint32_t a;
    asm("{ .reg .u64 t; cvta.to.shared.u64 t, %1; cvt.u32.u64 %0, t; }" : "=r"(a) : "l"(p));
    return a;
}
__device__ __forceinline__ void ldsm4(uint32_t r[4], uint32_t addr) {
    asm volatile("ldmatrix.sync.aligned.m8n8.x4.shared.b16 {%0,%1,%2,%3}, [%4];"
                 : "=r"(r[0]), "=r"(r[1]), "=r"(r[2]), "=r"(r[3]) : "r"(addr));
}
__device__ __forceinline__ void mma_bf16(float c[4], const uint32_t a[4],
                                         uint32_t b0, uint32_t b1) {
    asm volatile("mma.sync.aligned.m16n8k16.row.col.f32.bf16.bf16.f32 "
                 "{%0,%1,%2,%3}, {%4,%5,%6,%7}, {%8,%9}, {%0,%1,%2,%3};"
                 : "+f"(c[0]), "+f"(c[1]), "+f"(c[2]), "+f"(c[3])
                 : "r"(a[0]), "r"(a[1]), "r"(a[2]), "r"(a[3]), "r"(b0), "r"(b1));
}

// ---------------- main kernel ----------------
__global__ __launch_bounds__(128) void ct4d_mma(
    const float* __restrict__ bias, float* __restrict__ out)
{
    extern __shared__ char smem[];
    const int tid = threadIdx.x, lane = tid & 31, w = tid >> 5;
    const int c = blockIdx.z, b = blockIdx.y, tile = blockIdx.x;
    const int p1 = (c >> 3) & 1, p2 = (c >> 2) & 1, p3 = (c >> 1) & 1, p4 = c & 1;
    const int n1 = 13 - p1, n2 = 13 - p2, n3 = 13 - p3, n4 = 13 - p4;
    const int Ntot = n1 * n2 * n3 * n4;
    if (tile * 128 >= Ntot) return;
    const int lgT = 4 - p1 - p2 - p3 - p4;
    const int T = 1 << lgT;

    const uint32_t sb = smem_u32(smem);
    int*          kof  = (int*)(smem + SM_KOF);
    signed char (*dd)[4] = (signed char(*)[4])(smem + SM_DD);
    int*          offs = (int*)(smem + SM_OFFS);
    float*        bs   = (float*)(smem + SM_BIAS);

    if (tid < T) {
        int rem = tid, pp[4] = {p1, p2, p3, p4}, d[4], k[4];
        #pragma unroll
        for (int i = 0; i < 4; i++) {
            if (!pp[i]) { d[i] = rem & 1; rem >>= 1; k[i] = 2 * d[i]; }
            else        { d[i] = 0;                  k[i] = 1; }
        }
        kof[tid] = ((k[0] * 3 + k[1]) * 3 + k[2]) * 3 + k[3];
        dd[tid][0] = d[0]; dd[tid][1] = d[1]; dd[tid][2] = d[2]; dd[tid][3] = d[3];
    }
    if (tid < 64) bs[tid] = bias[tid];
    __syncthreads();

    // gather offsets: input row index in g_x{h,l} per (tap, sp), -1 = OOB/pad
    {
        int g = tile * 128 + tid;
        int valid = g < Ntot, m1 = 0, m2 = 0, m3 = 0, m4 = 0;
        if (valid) { m4 = g % n4; int q = g / n4; m3 = q % n3; q /= n3; m2 = q % n2; m1 = q / n2; }
        for (int t = 0; t < T; t++) {
            int off = -1;
            if (valid) {
                int a1 = m1 - dd[t][0], a2 = m2 - dd[t][1], a3 = m3 - dd[t][2], a4 = m4 - dd[t][3];
                if (((unsigned)a1 < 12u) & ((unsigned)a2 < 12u) & ((unsigned)a3 < 12u) & ((unsigned)a4 < 12u))
                    off = ((a1 * 12 + a2) * 12 + a3) * 12 + a4;
            }
            offs[t * 128 + tid] = off;
        }
    }

    const __nv_bfloat16* xhb = g_xh + (size_t)b * XM * 64;
    const __nv_bfloat16* xlb = g_xl + (size_t)b * XM * 64;

    float acc[2][8][4];
    #pragma unroll
    for (int i = 0; i < 2; i++)
        #pragma unroll
        for (int j = 0; j < 8; j++)
            #pragma unroll
            for (int q = 0; q < 4; q++) acc[i][j][q] = 0.f;

    for (int t = 0; t < T; t++) {
        __syncthreads();   // smem reuse barrier (and publishes offs on t==0)
        // stage B_hi/B_lo: 64 co rows x 128B (64 bf16 ci), XOR-swizzled
        {
            int co = tid >> 1, h = tid & 1;
            const uint4* srcH = (const uint4*)(g_wh + ((kof[t] * 64 + co) * 64 + h * 32));
            const uint4* srcL = (const uint4*)(g_wl + ((kof[t] * 64 + co) * 64 + h * 32));
            #pragma unroll
            for (int q = 0; q < 4; q++) {
                uint32_t bo = co * 128 + h * 64 + q * 16, so = SWZ(bo);
                *(uint4*)(smem + SM_BH + so) = srcH[q];
                *(uint4*)(smem + SM_BL + so) = srcL[q];
            }
        }
        // stage A_hi/A_lo: 128 sp rows x 128B
        {
            int off = offs[t * 128 + tid];
            const uint4 z = {0, 0, 0, 0};
            const uint4* sh = (off >= 0) ? (const uint4*)(xhb + (size_t)off * 64) : nullptr;
            const uint4* sl = (off >= 0) ? (const uint4*)(xlb + (size_t)off * 64) : nullptr;
            #pragma unroll
            for (int q = 0; q < 8; q++) {
                uint32_t bo = tid * 128 + q * 16, so = SWZ(bo);
                *(uint4*)(smem + SM_A  + so) = (off >= 0) ? sh[q] : z;
                *(uint4*)(smem + SM_AL + so) = (off >= 0) ? sl[q] : z;
            }
        }
        __syncthreads();

        // 128x64 x k64 GEMM slab: per warp 32(sp) x 64(co)
        #pragma unroll
        for (int kk = 0; kk < 4; kk++) {
            uint32_t Ah[2][4], Al[2][4];
            const uint32_t arow = w * 32 + (lane & 15);
            const uint32_t acol = kk * 32 + ((lane >> 4) & 1) * 16;
            #pragma unroll
            for (int i = 0; i < 2; i++) {
                uint32_t ao = SWZ((arow + i * 16) * 128 + acol);
                ldsm4(Ah[i], sb + SM_A  + ao);
                ldsm4(Al[i], sb + SM_AL + ao);
            }
            #pragma unroll
            for (int jp = 0; jp < 4; jp++) {
                uint32_t Bh[4], Bl[4];
                const uint32_t nrow = jp * 16 + (lane & 7) + ((lane >> 4) & 1) * 8;
                const uint32_t bcol = kk * 32 + ((lane >> 3) & 1) * 16;
                uint32_t bo = SWZ(nrow * 128 + bcol);
                ldsm4(Bh, sb + SM_BH + bo);
                ldsm4(Bl, sb + SM_BL + bo);
                #pragma unroll
                for (int i = 0; i < 2; i++) {
                    mma_bf16(acc[i][2 * jp],     Ah[i], Bh[0], Bh[1]);
                    mma_bf16(acc[i][2 * jp],     Ah[i], Bl[0], Bl[1]);
                    mma_bf16(acc[i][2 * jp],     Al[i], Bh[0], Bh[1]);
                    mma_bf16(acc[i][2 * jp + 1], Ah[i], Bh[2], Bh[3]);
                    mma_bf16(acc[i][2 * jp + 1], Ah[i], Bl[2], Bl[3]);
                    mma_bf16(acc[i][2 * jp + 1], Al[i], Bh[2], Bh[3]);
                }
            }
        }
    }

    // epilogue: fragment rows -> strided scatter into the class sub-grid
    float* ob = out + (size_t)b * OSB;
    const int gbase = tile * 128 + w * 32 + (lane >> 2);
    #pragma unroll
    for (int i = 0; i < 2; i++) {
        #pragma unroll
        for (int h = 0; h < 2; h++) {
            int g = gbase + i * 16 + h * 8;
            if (g >= Ntot) continue;
            int m4 = g % n4; int q = g / n4;
            int m3 = q % n3; q /= n3;
            int m2 = q % n2; int m1 = q / n2;
            long o = (long)(2 * m1 + p1) * OS1 + (2 * m2 + p2) * OS2 +
                     (2 * m3 + p3) * OS3 + (2 * m4 + p4);
            float* op = ob + o;
            #pragma unroll
            for (int j = 0; j < 8; j++) {
                int co = j * 8 + (lane & 3) * 2;
                op[(size_t)co * OSC]       = acc[i][j][2 * h]     + bs[co];
                op[(size_t)(co + 1) * OSC] = acc[i][j][2 * h + 1] + bs[co + 1];
            }
        }
    }
}

extern "C" void kernel_launch(void* const* d_in, const int* in_sizes, int n_in,
                              void* d_out, int out_size) {
    const float* x    = (const float*)d_in[0];
    const float* w    = (const float*)d_in[1];
    const float* bias = (const float*)d_in[2];
    float* out = (float*)d_out;

    cudaFuncSetAttribute(ct4d_mma, cudaFuncAttributeMaxDynamicSharedMemorySize, SM_TOTAL);

    wt_prep<<<1296, 256>>>(w);
    xt_prep<<<dim3(648, 4), 256>>>(x);
    ct4d_mma<<<dim3(224, 4, 16), 128, SM_TOTAL>>>(bias, out);
}

// round 5
// speedup vs baseline: 3.7084x; 1.4627x over previous
#include <cuda_runtime.h>
#include <cuda_bf16.h>
#include <cstdint>

// ---------------------------------------------------------------------------
// 4D ConvTranspose stride2 K=3^4 as 16 parity-class GEMMs on the legacy
// tensor-core path (ldmatrix + mma.sync m16n8k16 bf16, fp32 accum).
//   D[sp=256, co=64] += X[sp, k]·W[co, k],  k = (tap t, ci),  K = 64*T
// bf16 hi/lo split (xh*wh + xh*wl + xl*wh) for fp32-grade accuracy.
// R5: warp tile 64x64 (2x arithmetic intensity vs smem), cp.async staging.
// ---------------------------------------------------------------------------

#define XM 20736            // 12^4 input spatial points
#define OSB 25000000LL
#define OSC 390625
#define OS1 15625
#define OS2 625
#define OS3 25

// prepped operands
__device__ __align__(16) __nv_bfloat16 g_wh[81*64*64];   // [kidx][co][ci]
__device__ __align__(16) __nv_bfloat16 g_wl[81*64*64];
__device__ __align__(16) __nv_bfloat16 g_xh[4L*XM*64];   // [b][m_lin][ci]
__device__ __align__(16) __nv_bfloat16 g_xl[4L*XM*64];

// dynamic SMEM layout
#define SM_A    0           // A_hi: 256 rows x 128B = 32KB
#define SM_AL   32768       // A_lo: 32KB
#define SM_BH   65536       // B_hi: 64 rows x 128B = 8KB
#define SM_BL   73728       // B_lo: 8KB
#define SM_OFFS 81920       // u16[16*256] = 8KB
#define SM_BIAS 90112       // float[64]
#define SM_KOF  90368       // int[16]
#define SM_DD   90432       // char[16][4]
#define SM_TOTAL 90496

#define SWZ(o) ((o) ^ (((o) >> 3) & 0x70))

// ---------------- prep kernels ----------------
__global__ void wt_prep(const float* __restrict__ w) {
    int idx = blockIdx.x * 256 + threadIdx.x;
    if (idx >= 331776) return;                 // 64*64*81
    int ci = idx / 5184;
    int r  = idx - ci * 5184;
    int co = r / 81;
    int k  = r - co * 81;
    float v = w[idx];
    __nv_bfloat16 h = __float2bfloat16(v);
    __nv_bfloat16 l = __float2bfloat16(v - __bfloat162float(h));
    int o = (k * 64 + co) * 64 + ci;
    g_wh[o] = h; g_wl[o] = l;
}

__global__ void xt_prep(const float* __restrict__ x) {
    __shared__ float s[64][33];
    int b = blockIdx.y, m0 = blockIdx.x * 32, tid = threadIdx.x;
    for (int i = tid; i < 2048; i += 256) {
        int ci = i >> 5, mm = i & 31;
        s[ci][mm] = x[((size_t)(b * 64 + ci)) * XM + m0 + mm];
    }
    __syncthreads();
    int m = tid >> 3, q = tid & 7;
    union { __nv_bfloat16 a[8]; uint4 v; } hv, lv;
    #pragma unroll
    for (int j = 0; j < 8; j++) {
        float v = s[q * 8 + j][m];
        hv.a[j] = __float2bfloat16(v);
        lv.a[j] = __float2bfloat16(v - __bfloat162float(hv.a[j]));
    }
    size_t o = ((size_t)b * XM + m0 + m) * 64 + q * 8;
    *(uint4*)(g_xh + o) = hv.v;
    *(uint4*)(g_xl + o) = lv.v;
}

// ---------------- ptx helpers ----------------
__device__ __forceinline__ uint32_t smem_u32(const void* p) {
    uint32_t a;
    asm("{ .reg .u64 t; cvta.to.shared.u64 t, %1; cvt.u32.u64 %0, t; }" : "=r"(a) : "l"(p));
    return a;
}
__device__ __forceinline__ void ldsm4(uint32_t r[4], uint32_t addr) {
    asm volatile("ldmatrix.sync.aligned.m8n8.x4.shared.b16 {%0,%1,%2,%3}, [%4];"
                 : "=r"(r[0]), "=r"(r[1]), "=r"(r[2]), "=r"(r[3]) : "r"(addr));
}
__device__ __forceinline__ void mma_bf16(float c[4], const uint32_t a[4],
                                         uint32_t b0, uint32_t b1) {
    asm volatile("mma.sync.aligned.m16n8k16.row.col.f32.bf16.bf16.f32 "
                 "{%0,%1,%2,%3}, {%4,%5,%6,%7}, {%8,%9}, {%0,%1,%2,%3};"
                 : "+f"(c[0]), "+f"(c[1]), "+f"(c[2]), "+f"(c[3])
                 : "r"(a[0]), "r"(a[1]), "r"(a[2]), "r"(a[3]), "r"(b0), "r"(b1));
}
// 16B async copy, zero-fill when !pred
__device__ __forceinline__ void cpa16(uint32_t dst, const void* src, bool pred) {
    int sz = pred ? 16 : 0;
    asm volatile("cp.async.cg.shared.global [%0], [%1], 16, %2;"
                 :: "r"(dst), "l"(src), "r"(sz) : "memory");
}
__device__ __forceinline__ void cpa_wait_all() {
    asm volatile("cp.async.commit_group;" ::: "memory");
    asm volatile("cp.async.wait_group 0;" ::: "memory");
}

// ---------------- main kernel ----------------
__global__ __launch_bounds__(128) void ct4d_mma(
    const float* __restrict__ bias, float* __restrict__ out)
{
    extern __shared__ char smem[];
    const int tid = threadIdx.x, lane = tid & 31, w = tid >> 5;
    const int c = blockIdx.z, b = blockIdx.y, tile = blockIdx.x;
    const int p1 = (c >> 3) & 1, p2 = (c >> 2) & 1, p3 = (c >> 1) & 1, p4 = c & 1;
    const int n1 = 13 - p1, n2 = 13 - p2, n3 = 13 - p3, n4 = 13 - p4;
    const int Ntot = n1 * n2 * n3 * n4;
    if (tile * 256 >= Ntot) return;
    const int lgT = 4 - p1 - p2 - p3 - p4;
    const int T = 1 << lgT;

    const uint32_t sb = smem_u32(smem);
    int*          kof  = (int*)(smem + SM_KOF);
    signed char (*dd)[4] = (signed char(*)[4])(smem + SM_DD);
    uint16_t*     offs = (uint16_t*)(smem + SM_OFFS);
    float*        bs   = (float*)(smem + SM_BIAS);

    if (tid < T) {
        int rem = tid, pp[4] = {p1, p2, p3, p4}, d[4], k[4];
        #pragma unroll
        for (int i = 0; i < 4; i++) {
            if (!pp[i]) { d[i] = rem & 1; rem >>= 1; k[i] = 2 * d[i]; }
            else        { d[i] = 0;                  k[i] = 1; }
        }
        kof[tid] = ((k[0] * 3 + k[1]) * 3 + k[2]) * 3 + k[3];
        dd[tid][0] = d[0]; dd[tid][1] = d[1]; dd[tid][2] = d[2]; dd[tid][3] = d[3];
    }
    if (tid < 64) bs[tid] = bias[tid];
    __syncthreads();

    // gather offsets: input row index in g_x{h,l} per (tap, sp), 0xFFFF = OOB
    for (int s = tid; s < 256; s += 128) {
        int g = tile * 256 + s;
        int valid = g < Ntot, m1 = 0, m2 = 0, m3 = 0, m4 = 0;
        if (valid) { m4 = g % n4; int q = g / n4; m3 = q % n3; q /= n3; m2 = q % n2; m1 = q / n2; }
        for (int t = 0; t < T; t++) {
            int off = 0xFFFF;
            if (valid) {
                int a1 = m1 - dd[t][0], a2 = m2 - dd[t][1], a3 = m3 - dd[t][2], a4 = m4 - dd[t][3];
                if (((unsigned)a1 < 12u) & ((unsigned)a2 < 12u) & ((unsigned)a3 < 12u) & ((unsigned)a4 < 12u))
                    off = ((a1 * 12 + a2) * 12 + a3) * 12 + a4;
            }
            offs[t * 256 + s] = (uint16_t)off;
        }
    }

    const __nv_bfloat16* xhb = g_xh + (size_t)b * XM * 64;
    const __nv_bfloat16* xlb = g_xl + (size_t)b * XM * 64;

    float acc[4][8][4];
    #pragma unroll
    for (int i = 0; i < 4; i++)
        #pragma unroll
        for (int j = 0; j < 8; j++)
            #pragma unroll
            for (int q = 0; q < 4; q++) acc[i][j][q] = 0.f;

    const int q8 = tid & 7;          // 8 threads cooperate per 128B row
    const int rsub = tid >> 3;       // 16 rows per staging pass

    for (int t = 0; t < T; t++) {
        __syncthreads();   // prior MMA reads complete; offs published (t==0)

        // stage B_hi/B_lo: 64 co rows x 128B
        {
            const int kbase = kof[t] * 64;
            #pragma unroll
            for (int rb = 0; rb < 64; rb += 16) {
                int co = rb + rsub;
                uint32_t so = SWZ(co * 128 + q8 * 16);
                const __nv_bfloat16* sh = g_wh + (kbase + co) * 64 + q8 * 8;
                const __nv_bfloat16* sl = g_wl + (kbase + co) * 64 + q8 * 8;
                cpa16(sb + SM_BH + so, sh, true);
                cpa16(sb + SM_BL + so, sl, true);
            }
        }
        // stage A_hi/A_lo: 256 sp rows x 128B
        {
            const uint16_t* ot = offs + t * 256;
            #pragma unroll
            for (int rb = 0; rb < 256; rb += 16) {
                int r = rb + rsub;
                uint32_t off = ot[r];
                bool ok = off != 0xFFFFu;
                uint32_t so = SWZ(r * 128 + q8 * 16);
                size_t go = (size_t)off * 64 + q8 * 8;
                cpa16(sb + SM_A  + so, xhb + (ok ? go : 0), ok);
                cpa16(sb + SM_AL + so, xlb + (ok ? go : 0), ok);
            }
        }
        cpa_wait_all();
        __syncthreads();

        // 256x64 x k64 GEMM slab: per warp 64(sp) x 64(co)
        #pragma unroll
        for (int kk = 0; kk < 4; kk++) {
            uint32_t Ah[4][4], Al[4][4];
            const uint32_t acol = kk * 32 + ((lane >> 4) & 1) * 16;
            #pragma unroll
            for (int i = 0; i < 4; i++) {
                uint32_t ao = SWZ((w * 64 + i * 16 + (lane & 15)) * 128 + acol);
                ldsm4(Ah[i], sb + SM_A  + ao);
                ldsm4(Al[i], sb + SM_AL + ao);
            }
            #pragma unroll
            for (int jp = 0; jp < 4; jp++) {
                uint32_t Bh[4], Bl[4];
                const uint32_t nrow = jp * 16 + (lane & 7) + ((lane >> 4) & 1) * 8;
                const uint32_t bcol = kk * 32 + ((lane >> 3) & 1) * 16;
                uint32_t bo = SWZ(nrow * 128 + bcol);
                ldsm4(Bh, sb + SM_BH + bo);
                ldsm4(Bl, sb + SM_BL + bo);
                #pragma unroll
                for (int i = 0; i < 4; i++) {
                    mma_bf16(acc[i][2 * jp],     Ah[i], Bh[0], Bh[1]);
                    mma_bf16(acc[i][2 * jp],     Ah[i], Bl[0], Bl[1]);
                    mma_bf16(acc[i][2 * jp],     Al[i], Bh[0], Bh[1]);
                    mma_bf16(acc[i][2 * jp + 1], Ah[i], Bh[2], Bh[3]);
                    mma_bf16(acc[i][2 * jp + 1], Ah[i], Bl[2], Bl[3]);
                    mma_bf16(acc[i][2 * jp + 1], Al[i], Bh[2], Bh[3]);
                }
            }
        }
    }

    // epilogue: fragment rows -> strided scatter into the class sub-grid
    float* ob = out + (size_t)b * OSB;
    const int gbase = tile * 256 + w * 64 + (lane >> 2);
    #pragma unroll
    for (int i = 0; i < 4; i++) {
        #pragma unroll
        for (int h = 0; h < 2; h++) {
            int g = gbase + i * 16 + h * 8;
            if (g >= Ntot) continue;
            int m4 = g % n4; int q = g / n4;
            int m3 = q % n3; q /= n3;
            int m2 = q % n2; int m1 = q / n2;
            long o = (long)(2 * m1 + p1) * OS1 + (2 * m2 + p2) * OS2 +
                     (2 * m3 + p3) * OS3 + (2 * m4 + p4);
            float* op = ob + o;
            #pragma unroll
            for (int j = 0; j < 8; j++) {
                int co = j * 8 + (lane & 3) * 2;
                op[(size_t)co * OSC]       = acc[i][j][2 * h]     + bs[co];
                op[(size_t)(co + 1) * OSC] = acc[i][j][2 * h + 1] + bs[co + 1];
            }
        }
    }
}

extern "C" void kernel_launch(void* const* d_in, const int* in_sizes, int n_in,
                              void* d_out, int out_size) {
    const float* x    = (const float*)d_in[0];
    const float* w    = (const float*)d_in[1];
    const float* bias = (const float*)d_in[2];
    float* out = (float*)d_out;

    cudaFuncSetAttribute(ct4d_mma, cudaFuncAttributeMaxDynamicSharedMemorySize, SM_TOTAL);

    wt_prep<<<1296, 256>>>(w);
    xt_prep<<<dim3(648, 4), 256>>>(x);
    // 112 = ceil(13^4 / 256); smaller classes early-exit surplus tiles.
    ct4d_mma<<<dim3(112, 4, 16), 128, SM_TOTAL>>>(bias, out);
}